// round 2
// baseline (speedup 1.0000x reference)
#include <cuda_runtime.h>
#include <cfloat>
#include <math.h>

// Fixed problem shape (setup_inputs): N=8192, IN_F=512, OUT_F=64, C=2, k=32
#define N_     8192
#define INF_   512
#define OUTF_  64
#define C_     2
#define CAP    1024
#define KMAX   64

// Scratch for h = x @ W^T  [N_, OUTF_]  (2MB, device global: no allocations allowed)
__device__ float g_h[N_ * OUTF_];

// ---------------------------------------------------------------------------
// Kernel 1: h[n][f] = sum_kk x[n][kk] * W[f][kk]
// 256 threads = 4 rows x 64 outputs; x rows staged in smem; W hot in L1/L2.
// ---------------------------------------------------------------------------
__global__ void __launch_bounds__(256) h_kernel(const float* __restrict__ x,
                                                const float* __restrict__ W) {
    __shared__ float4 xs[4 * 128];  // 4 rows x 512 floats
    const int t = threadIdx.x;
    const int rowBase = blockIdx.x * 4;
    const float4* x4 = (const float4*)x;
#pragma unroll
    for (int i = 0; i < 2; i++) {
        int e = t + 256 * i;
        xs[e] = x4[(long)rowBase * 128 + e];
    }
    __syncthreads();
    const int rid = t >> 6;
    const int f   = t & 63;
    const float4* w4 = (const float4*)(W + f * INF_);
    const float4* xr = xs + rid * 128;
    float acc = 0.f;
#pragma unroll 8
    for (int kk = 0; kk < 128; kk++) {
        float4 a = xr[kk];
        float4 b = w4[kk];
        acc = fmaf(a.x, b.x, acc);
        acc = fmaf(a.y, b.y, acc);
        acc = fmaf(a.z, b.z, acc);
        acc = fmaf(a.w, b.w, acc);
    }
    g_h[(rowBase + rid) * OUTF_ + f] = acc;
}

// ---------------------------------------------------------------------------
// Kernel 2: per attention row (16384 blocks):
//   top-k (exact, jax tie-break), softmax over survivors, dense att row write,
//   and h_prime = att_row @ h scattered into the concat-transposed output.
// ---------------------------------------------------------------------------
__global__ void __launch_bounds__(256) topk_kernel(const float* __restrict__ araw,
                                                   const int*   __restrict__ kptr,
                                                   float*       __restrict__ out,
                                                   float*       __restrict__ att) {
    __shared__ float row[N_];          // 32KB: raw row, later reused as output row
    __shared__ float cval[CAP];
    __shared__ int   cidx[CAP];
    __shared__ int   sidx[KMAX];
    __shared__ float sw[KMAX];
    __shared__ float s_wmax[8];
    __shared__ int   s_cnt[3];
    __shared__ int   s_m;
    __shared__ float s_M;
    __shared__ float s_inv;
    __shared__ int   s_sel;

    const int t    = threadIdx.x;
    const int lane = t & 31;
    const int wid  = t >> 5;
    const long r   = blockIdx.x;

    int k = 32;
    if (kptr) { k = *kptr; if (k < 1) k = 1; if (k > KMAX) k = KMAX; }

    if (t == 0) { s_cnt[0] = 0; s_cnt[1] = 0; s_cnt[2] = 0; s_m = 0; }
    __syncthreads();

    // ---- load row (streaming), fused max + threshold counts ----
    const float4* src = (const float4*)(araw + r * (long)N_);
    float4* row4 = (float4*)row;
    float vmax = -FLT_MAX;
    int c0 = 0, c1 = 0, c2 = 0;
#pragma unroll
    for (int i = 0; i < 8; i++) {
        int e4 = t + 256 * i;
        float4 v = __ldcs(src + e4);
        row4[e4] = v;
        vmax = fmaxf(vmax, fmaxf(fmaxf(v.x, v.y), fmaxf(v.z, v.w)));
        c0 += (v.x >= 2.2f) + (v.y >= 2.2f) + (v.z >= 2.2f) + (v.w >= 2.2f);
        c1 += (v.x >= 1.2f) + (v.y >= 1.2f) + (v.z >= 1.2f) + (v.w >= 1.2f);
        c2 += (v.x >= 0.1f) + (v.y >= 0.1f) + (v.z >= 0.1f) + (v.w >= 0.1f);
    }
#pragma unroll
    for (int o = 16; o > 0; o >>= 1) {
        vmax = fmaxf(vmax, __shfl_xor_sync(0xffffffffu, vmax, o));
        c0 += __shfl_xor_sync(0xffffffffu, c0, o);
        c1 += __shfl_xor_sync(0xffffffffu, c1, o);
        c2 += __shfl_xor_sync(0xffffffffu, c2, o);
    }
    if (lane == 0) {
        s_wmax[wid] = vmax;
        atomicAdd(&s_cnt[0], c0);
        atomicAdd(&s_cnt[1], c1);
        atomicAdd(&s_cnt[2], c2);
    }
    __syncthreads();
    if (t == 0) {
        float m = s_wmax[0];
        for (int j = 1; j < 8; j++) m = fmaxf(m, s_wmax[j]);
        s_M = m;
        int sel = -1;
        if      (s_cnt[0] >= k && s_cnt[0] <= CAP) sel = 0;
        else if (s_cnt[1] >= k && s_cnt[1] <= CAP) sel = 1;
        else if (s_cnt[2] >= k && s_cnt[2] <= CAP) sel = 2;
        s_sel = sel;
    }
    __syncthreads();
    const float M  = s_M;
    const int  sel = s_sel;

    if (sel >= 0) {
        // ---- candidate extraction ----
        const float T = (sel == 0) ? 2.2f : ((sel == 1) ? 1.2f : 0.1f);
#pragma unroll
        for (int j = 0; j < 32; j++) {
            int e = t + 256 * j;
            float v = row[e];
            if (v >= T) {
                int pos = atomicAdd(&s_m, 1);
                cval[pos] = v;
                cidx[pos] = e;
            }
        }
        __syncthreads();
        const int m = s_m;
        // ---- exact rank (strict total order: value desc, index asc) ----
        for (int i = t; i < m; i += 256) {
            float vi = cval[i];
            int   ii = cidx[i];
            int rank = 0;
            for (int j = 0; j < m; j++) {
                float vj = cval[j];
                rank += (vj > vi) || (vj == vi && cidx[j] < ii);
            }
            if (rank < k) { sidx[rank] = ii; sw[rank] = expf(vi - M); }
        }
    } else {
        // ---- exact brute-force fallback (degenerate distributions only) ----
        for (int j = 0; j < 32; j++) {
            int e = t + 256 * j;
            float v = row[e];
            int rank = 0;
            for (int q = 0; q < N_ && rank < k; q++) {
                float u = row[q];
                rank += (u > v) || (u == v && q < e);
            }
            if (rank < k) { sidx[rank] = e; sw[rank] = expf(v - M); }
        }
    }
    __syncthreads();

    // ---- deterministic softmax denominator (serial over rank order) ----
    if (t == 0) {
        float s = 0.f;
        for (int j = 0; j < k; j++) s += sw[j];
        s_inv = 1.0f / s;
    }
    __syncthreads();
    const float inv = s_inv;

    // ---- rebuild the row as the sparse softmax output ----
#pragma unroll
    for (int i = 0; i < 8; i++) row4[t + 256 * i] = make_float4(0.f, 0.f, 0.f, 0.f);
    __syncthreads();
    if (t < k) row[sidx[t]] = sw[t] * inv;
    __syncthreads();

    if (att) {
        float4* dst = (float4*)(att + r * (long)N_);
#pragma unroll
        for (int i = 0; i < 8; i++) {
            int e4 = t + 256 * i;
            __stcs(dst + e4, row4[e4]);
        }
    }

    // ---- h_prime row -> concat-transposed output [n, c*OUTF + f] ----
    if (out && t < OUTF_) {
        float acc = 0.f;
        for (int p = 0; p < k; p++)
            acc = fmaf(sw[p] * inv, g_h[sidx[p] * OUTF_ + t], acc);
        const int c = (int)(r / N_);
        const int n = (int)(r % N_);
        out[(long)n * (C_ * OUTF_) + c * OUTF_ + t] = acc;
    }
}

// ---------------------------------------------------------------------------
extern "C" void kernel_launch(void* const* d_in, const int* in_sizes, int n_in,
                              void* d_out, int out_size) {
    const float* x    = (const float*)d_in[0];
    const float* W    = (const float*)d_in[1];
    const float* araw = (const float*)d_in[2];
    const int*   kptr = (n_in > 3) ? (const int*)d_in[3] : nullptr;

    const long attElems = (long)in_sizes[2];        // R * N
    const int  R        = (int)(attElems / N_);     // 16384
    const long outElems = (long)N_ * C_ * OUTF_;    // 1,048,576

    float* outp = nullptr;
    float* attp = nullptr;
    const long osz = (long)out_size;
    if (osz >= outElems + attElems) {
        outp = (float*)d_out;
        attp = (float*)d_out + outElems;   // tuple order: (out, att)
    } else if (osz == attElems) {
        attp = (float*)d_out;
    } else {
        outp = (float*)d_out;
    }

    if (outp) h_kernel<<<N_ / 4, 256>>>(x, W);
    topk_kernel<<<R, 256>>>(araw, kptr, outp, attp);
}

// round 4
// speedup vs baseline: 1.8038x; 1.8038x over previous
#include <cuda_runtime.h>
#include <cfloat>
#include <math.h>

// Fixed problem shape (setup_inputs): N=8192, IN_F=512, OUT_F=64, C=2, k=32
#define N_     8192
#define INF_   512
#define OUTF_  64
#define C_     2
#define CAP    1024
#define KMAX   64
#define T0     2.2f

// Scratch for h = x @ W^T  [N_, OUTF_]  (2MB, device global: no allocations allowed)
__device__ float g_h[N_ * OUTF_];

__device__ __forceinline__ unsigned long long fma2(unsigned long long a,
                                                   unsigned long long b,
                                                   unsigned long long c) {
    unsigned long long d;
    asm("fma.rn.f32x2 %0, %1, %2, %3;" : "=l"(d) : "l"(a), "l"(b), "l"(c));
    return d;
}

// ---------------------------------------------------------------------------
// Kernel 1: h[n][f] = sum_kk x[n][kk] * W[f][kk]
// 16 rows/block; warp-uniform smem x reads (broadcast); 4 rows/thread;
// packed f32x2 FMA (2 MACs/instr).
// ---------------------------------------------------------------------------
__global__ void __launch_bounds__(256) h_kernel(const float* __restrict__ x,
                                                const float* __restrict__ W) {
    __shared__ float4 xs[16 * 128];  // 16 rows x 512 floats = 32KB
    const int t = threadIdx.x;
    const int rowBase = blockIdx.x * 16;
    const float4* x4 = (const float4*)x;
#pragma unroll
    for (int i = 0; i < 8; i++) {
        int e = t + 256 * i;
        xs[e] = x4[(long)rowBase * 128 + e];
    }
    __syncthreads();

    const int f  = t & 63;
    const int rg = t >> 6;  // 0..3 -> local rows rg*4 .. rg*4+3 (warp-uniform)
    const ulonglong2* __restrict__ w2  = (const ulonglong2*)(W + f * INF_);
    const ulonglong2* __restrict__ xs2 = (const ulonglong2*)xs;

    unsigned long long acc[4] = {0ull, 0ull, 0ull, 0ull};
#pragma unroll 4
    for (int kk = 0; kk < 128; kk++) {
        ulonglong2 b = w2[kk];
#pragma unroll
        for (int j = 0; j < 4; j++) {
            ulonglong2 a = xs2[(rg * 4 + j) * 128 + kk];  // warp broadcast
            acc[j] = fma2(a.x, b.x, acc[j]);
            acc[j] = fma2(a.y, b.y, acc[j]);
        }
    }
#pragma unroll
    for (int j = 0; j < 4; j++) {
        float lo = __uint_as_float((unsigned)(acc[j] & 0xffffffffu));
        float hi = __uint_as_float((unsigned)(acc[j] >> 32));
        g_h[(rowBase + rg * 4 + j) * OUTF_ + f] = lo + hi;
    }
}

// ---------------------------------------------------------------------------
// Kernel 2: per attention row (16384 blocks):
//   candidates >= T0 extracted during the global load (no smem row),
//   exact rank (jax tie-break), softmax, direct sparse att write,
//   h_prime gather into concat-transposed output.
// ---------------------------------------------------------------------------
__global__ void __launch_bounds__(256) topk_kernel(const float* __restrict__ araw,
                                                   const int*   __restrict__ kptr,
                                                   float*       __restrict__ out,
                                                   float*       __restrict__ att) {
    __shared__ float cval[CAP];
    __shared__ int   cidx[CAP];
    __shared__ int   sidx[KMAX];
    __shared__ float sw[KMAX];
    __shared__ float s_wmax[8];
    __shared__ float s_bv[8];
    __shared__ int   s_bi[8];
    __shared__ int   s_m;
    __shared__ float s_M;
    __shared__ float s_inv;
    __shared__ float s_lastV;
    __shared__ int   s_lastI;

    const int t    = threadIdx.x;
    const int lane = t & 31;
    const int wid  = t >> 5;
    const long r   = blockIdx.x;

    int k = 32;
    if (kptr) { k = *kptr; if (k < 1) k = 1; if (k > KMAX) k = KMAX; }

    if (t == 0) s_m = 0;
    __syncthreads();

    // ---- streaming load: fused max + candidate extraction (>= T0) ----
    const float4* src = (const float4*)(araw + r * (long)N_);
    float vmax = -FLT_MAX;
#pragma unroll
    for (int i = 0; i < 8; i++) {
        int e4 = t + 256 * i;
        float4 v = __ldcs(src + e4);
        vmax = fmaxf(vmax, fmaxf(fmaxf(v.x, v.y), fmaxf(v.z, v.w)));
        int base = 4 * e4;
        if (v.x >= T0) { int p = atomicAdd(&s_m, 1); if (p < CAP) { cval[p] = v.x; cidx[p] = base;     } }
        if (v.y >= T0) { int p = atomicAdd(&s_m, 1); if (p < CAP) { cval[p] = v.y; cidx[p] = base + 1; } }
        if (v.z >= T0) { int p = atomicAdd(&s_m, 1); if (p < CAP) { cval[p] = v.z; cidx[p] = base + 2; } }
        if (v.w >= T0) { int p = atomicAdd(&s_m, 1); if (p < CAP) { cval[p] = v.w; cidx[p] = base + 3; } }
    }
#pragma unroll
    for (int o = 16; o > 0; o >>= 1)
        vmax = fmaxf(vmax, __shfl_xor_sync(0xffffffffu, vmax, o));
    if (lane == 0) s_wmax[wid] = vmax;
    __syncthreads();
    if (t == 0) {
        float m = s_wmax[0];
#pragma unroll
        for (int j = 1; j < 8; j++) m = fmaxf(m, s_wmax[j]);
        s_M = m;
    }
    __syncthreads();
    const float M = s_M;
    const int   m = s_m;

    if (m >= k && m <= CAP) {
        // ---- exact rank over candidates (value desc, index asc) ----
        for (int i = t; i < m; i += 256) {
            float vi = cval[i];
            int   ii = cidx[i];
            int rank = 0;
            for (int j = 0; j < m; j++) {
                float vj = cval[j];
                rank += (vj > vi) || (vj == vi && cidx[j] < ii);
            }
            if (rank < k) { sidx[rank] = ii; sw[rank] = expf(vi - M); }
        }
        __syncthreads();
    } else {
        // ---- robust fallback: k deterministic arg-max passes over global ----
        if (t == 0) { s_lastV = FLT_MAX; s_lastI = -1; }
        __syncthreads();
        const float* rowg = araw + r * (long)N_;
        for (int p = 0; p < k; p++) {
            float lastV = s_lastV; int lastI = s_lastI;
            float bv = -FLT_MAX; int bi = N_;
            for (int e = t; e < N_; e += 256) {
                float v = rowg[e];
                bool after = (v < lastV) || (v == lastV && e > lastI);
                if (after && ((v > bv) || (v == bv && e < bi))) { bv = v; bi = e; }
            }
#pragma unroll
            for (int o = 16; o > 0; o >>= 1) {
                float ov = __shfl_xor_sync(0xffffffffu, bv, o);
                int   oi = __shfl_xor_sync(0xffffffffu, bi, o);
                if ((ov > bv) || (ov == bv && oi < bi)) { bv = ov; bi = oi; }
            }
            if (lane == 0) { s_bv[wid] = bv; s_bi[wid] = bi; }
            __syncthreads();
            if (t == 0) {
                float gv = s_bv[0]; int gi = s_bi[0];
#pragma unroll
                for (int j = 1; j < 8; j++) {
                    if ((s_bv[j] > gv) || (s_bv[j] == gv && s_bi[j] < gi)) { gv = s_bv[j]; gi = s_bi[j]; }
                }
                sidx[p] = gi; sw[p] = expf(gv - M);
                s_lastV = gv; s_lastI = gi;
            }
            __syncthreads();
        }
    }

    // ---- deterministic softmax denominator (serial over rank order) ----
    if (t == 0) {
        float s = 0.f;
        for (int j = 0; j < k; j++) s += sw[j];
        s_inv = 1.0f / s;
    }
    __syncthreads();
    const float inv = s_inv;

    // ---- sparse att row: streaming zeros, then scatter the k values ----
    if (att) {
        float4* dst = (float4*)(att + r * (long)N_);
        const float4 z = make_float4(0.f, 0.f, 0.f, 0.f);
#pragma unroll
        for (int i = 0; i < 8; i++) __stcs(dst + t + 256 * i, z);
        __syncthreads();   // order zero-fill before scatter (block-wide fence)
        if (t < k) att[r * (long)N_ + sidx[t]] = sw[t] * inv;
    }

    // ---- h_prime row -> concat-transposed output [n, c*OUTF + f] ----
    if (out && t < OUTF_) {
        float acc = 0.f;
        for (int p = 0; p < k; p++)
            acc = fmaf(sw[p] * inv, g_h[sidx[p] * OUTF_ + t], acc);
        const int c = (int)(r / N_);
        const int n = (int)(r % N_);
        out[(long)n * (C_ * OUTF_) + c * OUTF_ + t] = acc;
    }
}

// ---------------------------------------------------------------------------
extern "C" void kernel_launch(void* const* d_in, const int* in_sizes, int n_in,
                              void* d_out, int out_size) {
    const float* x    = (const float*)d_in[0];
    const float* W    = (const float*)d_in[1];
    const float* araw = (const float*)d_in[2];
    const int*   kptr = (n_in > 3) ? (const int*)d_in[3] : nullptr;

    const long attElems = (long)in_sizes[2];        // R * N
    const int  R        = (int)(attElems / N_);     // 16384
    const long outElems = (long)N_ * C_ * OUTF_;    // 1,048,576

    float* outp = nullptr;
    float* attp = nullptr;
    const long osz = (long)out_size;
    if (osz >= outElems + attElems) {
        outp = (float*)d_out;
        attp = (float*)d_out + outElems;   // tuple order: (out, att)
    } else if (osz == attElems) {
        attp = (float*)d_out;
    } else {
        outp = (float*)d_out;
    }

    if (outp) h_kernel<<<N_ / 16, 256>>>(x, W);
    topk_kernel<<<R, 256>>>(araw, kptr, outp, attp);
}